// round 12
// baseline (speedup 1.0000x reference)
#include <cuda_runtime.h>
#include <cuda_bf16.h>
#include <cstdint>
#include <math.h>

#define BB 4
#define SS 4096
#define DD 256
#define D2 512

// ---- scratch (static __device__ globals; no allocation anywhere) ----
__device__ __nv_bfloat16 g_q[(size_t)BB * SS * DD];    // q bf16 (8 MB)
__device__ __nv_bfloat16 g_k[(size_t)BB * SS * DD];    // k bf16 (8 MB)
__device__ __nv_bfloat16 g_P[(size_t)BB * SS * SS];    // exp(logits) bf16 (134 MB)
__device__ float         g_z[BB * SS];                 // per-row sum-exp

// ===========================================================================
// helpers
// ===========================================================================
__device__ __forceinline__ uint32_t smem_u32(const void* p) {
    uint32_t a;
    asm("{ .reg .u64 t; cvta.to.shared.u64 t, %1; cvt.u32.u64 %0, t; }" : "=r"(a) : "l"(p));
    return a;
}
__device__ __forceinline__ void ldmx4(uint32_t* r, uint32_t addr) {
    asm volatile("ldmatrix.sync.aligned.m8n8.x4.shared.b16 {%0,%1,%2,%3}, [%4];"
                 : "=r"(r[0]), "=r"(r[1]), "=r"(r[2]), "=r"(r[3]) : "r"(addr));
}
__device__ __forceinline__ void ldmx2(uint32_t* r, uint32_t addr) {
    asm volatile("ldmatrix.sync.aligned.m8n8.x2.shared.b16 {%0,%1}, [%2];"
                 : "=r"(r[0]), "=r"(r[1]) : "r"(addr));
}
__device__ __forceinline__ void mma16816(float* c, const uint32_t* a, const uint32_t* b) {
    asm volatile(
        "mma.sync.aligned.m16n8k16.row.col.f32.bf16.bf16.f32 "
        "{%0,%1,%2,%3}, {%4,%5,%6,%7}, {%8,%9}, {%0,%1,%2,%3};"
        : "+f"(c[0]), "+f"(c[1]), "+f"(c[2]), "+f"(c[3])
        : "r"(a[0]), "r"(a[1]), "r"(a[2]), "r"(a[3]), "r"(b[0]), "r"(b[1]));
}
__device__ __forceinline__ uint32_t pack_bf16(float x, float y) {
    return (uint32_t)__bfloat16_as_ushort(__float2bfloat16_rn(x))
         | ((uint32_t)__bfloat16_as_ushort(__float2bfloat16_rn(y)) << 16);
}
__device__ __forceinline__ void cp_async16(uint32_t dst, const void* src) {
    asm volatile("cp.async.cg.shared.global [%0], [%1], 16;" :: "r"(dst), "l"(src) : "memory");
}
// exact bf16 -> fp32 (bit shift)
__device__ __forceinline__ float bflo(uint32_t w) { return __uint_as_float(w << 16); }
__device__ __forceinline__ float bfhi(uint32_t w) { return __uint_as_float(w & 0xFFFF0000u); }

#define PADB 80          // bytes per smem tile row (64B data + 16B pad)
// ---- logits (128q x 64k CTA) ----
#define LGS_B_OFF 10240                  // B rows start (A = 128 rows)
#define LGS_STAGE (10240 + 64 * PADB)    // 15360 B per stage
#define LG_SMEM   (3 * LGS_STAGE)        // 46080
// ---- proj ----
#define PR_SMEM (2 * 128 * PADB)

// ===========================================================================
// zero: clear g_z and d_out each replay (g_w no longer exists)
// ===========================================================================
__global__ void zero_kernel(float* out, int n_out) {
    int i = blockIdx.x * blockDim.x + threadIdx.x;
    if (i < BB * SS) g_z[i] = 0.0f;
    if (i < n_out)   out[i] = 0.0f;
}

// ===========================================================================
// probe: empty kernel occupying the 3rd launch slot so logits_kernel lands
// in the ncu-captured 4th slot.
// ===========================================================================
__global__ void probe_kernel() {}

// ===========================================================================
// projection: qk[B*S,512] = x @ W^T + bias, single bf16 HMMA (passing, kept)
// ===========================================================================
__global__ __launch_bounds__(256, 2) void proj_kernel(
    const float* __restrict__ x, const float* __restrict__ W,
    const float* __restrict__ bias)
{
    __shared__ __align__(16) char tiles[PR_SMEM];

    const int tid = threadIdx.x;
    const int lane = tid & 31, wid = tid >> 5;
    const int wm = wid >> 2, wn = wid & 3;

    const float* Ab = x + (size_t)blockIdx.y * 128 * DD;
    const float* Bb = W + (size_t)blockIdx.x * 128 * DD;
    const uint32_t sb = smem_u32(tiles);

    float acc[4][4][4];
#pragma unroll
    for (int m = 0; m < 4; m++)
#pragma unroll
        for (int n = 0; n < 4; n++)
#pragma unroll
            for (int u = 0; u < 4; u++) acc[m][n][u] = 0.0f;

    const uint32_t a_row = (uint32_t)(lane & 15);
    const uint32_t a_koff = (uint32_t)((lane >> 4) << 4);
    const uint32_t b_row = (uint32_t)(lane & 7);
    const uint32_t b_koff = (uint32_t)(((lane >> 3) & 1) << 4);

    for (int kt = 0; kt < 8; kt++) {
        __syncthreads();
#pragma unroll
        for (int i = 0; i < 8; i++) {
            int chunk = tid + i * 256;
            int arr = chunk >> 10;
            int c = chunk & 1023;
            int row = c >> 3, c4 = c & 7;
            const float* src = (arr ? Bb : Ab) + (size_t)row * DD + kt * 32 + c4 * 4;
            float4 v = *reinterpret_cast<const float4*>(src);
            uint2 p;
            p.x = pack_bf16(v.x, v.y);
            p.y = pack_bf16(v.z, v.w);
            *reinterpret_cast<uint2*>(tiles + arr * 10240 + row * PADB + c4 * 8) = p;
        }
        __syncthreads();

#pragma unroll
        for (int k16 = 0; k16 < 2; k16++) {
            const uint32_t kb = (uint32_t)(k16 * 32);
            uint32_t bh[4][2];
#pragma unroll
            for (int n = 0; n < 4; n++) {
                uint32_t boff = (uint32_t)(wn * 32 + n * 8 + b_row) * PADB + kb + b_koff;
                ldmx2(bh[n], sb + 10240 + boff);
            }
#pragma unroll
            for (int m = 0; m < 4; m++) {
                uint32_t aoff = (uint32_t)(wm * 64 + m * 16 + a_row) * PADB + kb + a_koff;
                uint32_t ah[4];
                ldmx4(ah, sb + aoff);
#pragma unroll
                for (int n = 0; n < 4; n++)
                    mma16816(acc[m][n], ah, bh[n]);
            }
        }
    }

    const int g = lane >> 2, t2 = (lane & 3) * 2;
#pragma unroll
    for (int m = 0; m < 4; m++) {
        const size_t grow = (size_t)blockIdx.y * 128 + wm * 64 + m * 16 + g;
#pragma unroll
        for (int n = 0; n < 4; n++) {
            const int col = blockIdx.x * 128 + wn * 32 + n * 8 + t2;
            const float b0 = bias[col], b1 = bias[col + 1];
            uint32_t p01 = pack_bf16(acc[m][n][0] + b0, acc[m][n][1] + b1);
            uint32_t p23 = pack_bf16(acc[m][n][2] + b0, acc[m][n][3] + b1);
            __nv_bfloat16* base = (col < DD) ? (g_q + col) : (g_k + (col - DD));
            *reinterpret_cast<uint32_t*>(base + grow * DD)       = p01;
            *reinterpret_cast<uint32_t*>(base + (grow + 8) * DD) = p23;
        }
    }
}

// ===========================================================================
// logits kernel: CTA = 128(q) x 64(k), K=256, single bf16 HMMA.
// 256 thr / 8 warps in 4m x 2n, warp tile 32x32, 4 CTAs/SM (64-reg budget).
// 3-stage cp.async, hoisted ldmatrix bases.
// Epilogue: exp -> DIRECT 4B STG (no smem staging); z row sums.
// ===========================================================================
__global__ __launch_bounds__(256, 4) void logits_kernel() {
    extern __shared__ __align__(16) char tiles[];
    __shared__ float zrow[128];

    const int tid = threadIdx.x;
    const int lane = tid & 31, wid = tid >> 5;
    const int wm = wid & 3, wn = wid >> 2;      // 4 m-groups x 2 n-groups
    const int nt = blockIdx.x, qt = blockIdx.y, b = blockIdx.z;

    if (tid < 128) zrow[tid] = 0.0f;

    const uint32_t sb = smem_u32(tiles);
    const __nv_bfloat16* Qs = g_q + ((size_t)b * SS + (size_t)qt * 128) * DD;
    const __nv_bfloat16* Ks = g_k + ((size_t)b * SS + (size_t)nt * 64) * DD;

    float acc[2][4][4];
#pragma unroll
    for (int m = 0; m < 2; m++)
#pragma unroll
        for (int n = 0; n < 4; n++)
#pragma unroll
            for (int u = 0; u < 4; u++) acc[m][n][u] = 0.0f;

    // hoisted per-thread ldmatrix base addresses (smem absolute, stage 0)
    const uint32_t x4_row = (uint32_t)(lane & 15);
    const uint32_t x4_koff = (uint32_t)((lane >> 4) << 4);
    const uint32_t a_base0 = sb + (uint32_t)(wm * 32 + x4_row) * PADB + x4_koff;
    const uint32_t a_base1 = a_base0 + 16 * PADB;
    const uint32_t b_base0 = sb + LGS_B_OFF + (uint32_t)(wn * 32 + x4_row) * PADB + x4_koff;
    const uint32_t b_base1 = b_base0 + 16 * PADB;

    const int ch_isB[3]  = { tid >= 512 ? 1 : 0, (tid + 256) >= 512 ? 1 : 0, 1 };

#define LOAD_STAGE(kt, s)                                                        \
    do {                                                                         \
        _Pragma("unroll")                                                        \
        for (int i = 0; i < 3; i++) {                                            \
            int chunk = tid + i * 256;                                           \
            int isB = ch_isB[i];                                                 \
            int c = chunk - (isB ? 512 : 0);                                     \
            int row = c >> 2, c4 = c & 3;                                        \
            const __nv_bfloat16* src = (isB ? Ks : Qs) + (size_t)row * DD + (kt) * 32 + c4 * 8; \
            cp_async16(sb + (uint32_t)(s) * LGS_STAGE + (isB ? LGS_B_OFF : 0) + row * PADB + c4 * 16, src); \
        }                                                                        \
        asm volatile("cp.async.commit_group;" ::: "memory");                     \
    } while (0)

    LOAD_STAGE(0, 0);
    LOAD_STAGE(1, 1);

    int stage = 0;
    for (int kt = 0; kt < 8; kt++) {
        if (kt < 7) asm volatile("cp.async.wait_group 1;" ::: "memory");
        else        asm volatile("cp.async.wait_group 0;" ::: "memory");
        __syncthreads();
        if (kt + 2 < 8) {
            int ns = stage + 2; if (ns >= 3) ns -= 3;
            LOAD_STAGE(kt + 2, ns);
        }

        const uint32_t soff = (uint32_t)stage * LGS_STAGE;
#pragma unroll
        for (int k16 = 0; k16 < 2; k16++) {
            const uint32_t kb = soff + (uint32_t)(k16 * 32);
            uint32_t br[2][4];
            ldmx4(br[0], b_base0 + kb);
            ldmx4(br[1], b_base1 + kb);
            uint32_t ah[4];
            ldmx4(ah, a_base0 + kb);
#pragma unroll
            for (int nn = 0; nn < 2; nn++) {
                uint32_t b0[2] = { br[nn][0], br[nn][2] };
                uint32_t b1[2] = { br[nn][1], br[nn][3] };
                mma16816(acc[0][nn * 2 + 0], ah, b0);
                mma16816(acc[0][nn * 2 + 1], ah, b1);
            }
            ldmx4(ah, a_base1 + kb);
#pragma unroll
            for (int nn = 0; nn < 2; nn++) {
                uint32_t b0[2] = { br[nn][0], br[nn][2] };
                uint32_t b1[2] = { br[nn][1], br[nn][3] };
                mma16816(acc[1][nn * 2 + 0], ah, b0);
                mma16816(acc[1][nn * 2 + 1], ah, b1);
            }
        }
        if (++stage == 3) stage = 0;
    }

    // ---- epilogue: exp, DIRECT 4B global stores, z row sums ----
    const int g = lane >> 2, t2 = (lane & 3) * 2;
    const size_t grow0 = (size_t)b * SS + (size_t)qt * 128;
    const int col0 = nt * 64 + wn * 32 + t2;
#pragma unroll
    for (int m = 0; m < 2; m++) {
        const int row_lo = wm * 32 + m * 16 + g;
        const size_t rbase = (grow0 + row_lo) * SS;
        float zlo = 0.0f, zhi = 0.0f;
#pragma unroll
        for (int n = 0; n < 4; n++) {
            float e0 = __expf(acc[m][n][0] * 0.0625f);
            float e1 = __expf(acc[m][n][1] * 0.0625f);
            float e2 = __expf(acc[m][n][2] * 0.0625f);
            float e3 = __expf(acc[m][n][3] * 0.0625f);
            zlo += e0 + e1;
            zhi += e2 + e3;
            const int col = col0 + n * 8;
            *reinterpret_cast<uint32_t*>(g_P + rbase + col)            = pack_bf16(e0, e1);
            *reinterpret_cast<uint32_t*>(g_P + rbase + 8 * SS + col)   = pack_bf16(e2, e3);
        }
        atomicAdd(&zrow[row_lo], zlo);
        atomicAdd(&zrow[row_lo + 8], zhi);
    }
    __syncthreads();
    if (tid < 128)
        atomicAdd(&g_z[grow0 + tid], zrow[tid]);
}

// ===========================================================================
// fused column weights + pool:  block = (batch, 128 cols), all 4096 rows.
//   w_k = sum_q P[q,k] / z_q      (register acc + smem cross-stripe reduce)
//   out[b,d] += sum_{k in block} w_k * x[b,k,d]
// No g_w array, no row-partition atomics, no separate out kernel.
// ===========================================================================
__global__ __launch_bounds__(256) void colw_out_kernel(
    const float* __restrict__ x, float* __restrict__ out)
{
    __shared__ float izs[SS];         // 16 KB: 1/z for all rows of this batch
    __shared__ float ws[16][128];     // 8 KB cross-stripe reduce
    __shared__ float wcol[128];

    const int tid = threadIdx.x;
    const int c0 = blockIdx.x * 128;
    const int b  = blockIdx.y;

    for (int i = tid; i < SS; i += 256)
        izs[i] = 1.0f / g_z[(size_t)b * SS + i];
    __syncthreads();

    const int c8 = tid & 15;          // 16 chunks of 8 cols
    const int rstripe = tid >> 4;     // 16 row stripes

    float acc[8];
#pragma unroll
    for (int j = 0; j < 8; j++) acc[j] = 0.0f;

    const __nv_bfloat16* Pb = g_P + ((size_t)b * SS + rstripe) * SS + c0 + c8 * 8;
#pragma unroll 4
    for (int i = 0; i < 256; i++) {           // 4096 rows / 16 stripes
        const float iz = izs[rstripe + i * 16];
        uint4 v = *reinterpret_cast<const uint4*>(Pb + (size_t)i * 16 * SS);
        const uint32_t w[4] = {v.x, v.y, v.z, v.w};
#pragma unroll
        for (int h = 0; h < 4; h++) {
            acc[2 * h]     = fmaf(bflo(w[h]), iz, acc[2 * h]);
            acc[2 * h + 1] = fmaf(bfhi(w[h]), iz, acc[2 * h + 1]);
        }
    }

#pragma unroll
    for (int j = 0; j < 8; j++) ws[rstripe][c8 * 8 + j] = acc[j];
    __syncthreads();

    if (tid < 128) {
        float s = 0.0f;
#pragma unroll
        for (int j = 0; j < 16; j++) s += ws[j][tid];
        wcol[tid] = s;
    }
    __syncthreads();

    // ---- pool this block's 128 keys: out[b, d=tid] += sum_k w_k * x[b,k,d]
    const float* xp = x + ((size_t)b * SS + c0) * DD + tid;
    float a0 = 0.0f, a1 = 0.0f, a2 = 0.0f, a3 = 0.0f;
#pragma unroll 8
    for (int kk = 0; kk < 128; kk += 4) {
        a0 = fmaf(wcol[kk + 0], xp[(size_t)(kk + 0) * DD], a0);
        a1 = fmaf(wcol[kk + 1], xp[(size_t)(kk + 1) * DD], a1);
        a2 = fmaf(wcol[kk + 2], xp[(size_t)(kk + 2) * DD], a2);
        a3 = fmaf(wcol[kk + 3], xp[(size_t)(kk + 3) * DD], a3);
    }
    atomicAdd(&out[b * DD + tid], (a0 + a1) + (a2 + a3));
}

// ===========================================================================
extern "C" void kernel_launch(void* const* d_in, const int* in_sizes, int n_in,
                              void* d_out, int out_size) {
    const float* x    = (const float*)d_in[0];
    const float* W    = (const float*)d_in[1];
    const float* bias = (const float*)d_in[2];
    float* out = (float*)d_out;

    cudaFuncSetAttribute(logits_kernel, cudaFuncAttributeMaxDynamicSharedMemorySize, LG_SMEM);

    // 0) zero g_z + out                                      (launch #1)
    zero_kernel<<<64, 256>>>(out, out_size);

    // 1) projection                                          (launch #2)
    {
        dim3 grid(D2 / 128, (BB * SS) / 128);
        proj_kernel<<<grid, 256>>>(x, W, bias);
    }

    // probe: shifts logits into the profiled 4th slot        (launch #3)
    probe_kernel<<<1, 32>>>();

    // 2) logits + exp + z  (direct-STG epilogue)             (launch #4)
    {
        dim3 grid(SS / 64, SS / 128, BB);
        logits_kernel<<<grid, 256, LG_SMEM>>>();
    }

    // 3) fused column weights + pool                         (launch #5)
    {
        dim3 grid(SS / 128, BB);
        colw_out_kernel<<<grid, 256>>>(x, out);
    }
}

// round 13
// speedup vs baseline: 1.3255x; 1.3255x over previous
#include <cuda_runtime.h>
#include <cuda_bf16.h>
#include <cstdint>
#include <math.h>

#define BB 4
#define SS 4096
#define DD 256
#define D2 512

// ---- scratch (static __device__ globals; no allocation anywhere) ----
__device__ __nv_bfloat16 g_q[(size_t)BB * SS * DD];    // q bf16 (8 MB)
__device__ __nv_bfloat16 g_k[(size_t)BB * SS * DD];    // k bf16 (8 MB)
__device__ __nv_bfloat16 g_P[(size_t)BB * SS * SS];    // exp(logits) bf16 (134 MB)
__device__ float         g_z[BB * SS];                 // per-row sum-exp
__device__ float         g_w[BB * SS];                 // column weights

// ===========================================================================
// helpers
// ===========================================================================
__device__ __forceinline__ uint32_t smem_u32(const void* p) {
    uint32_t a;
    asm("{ .reg .u64 t; cvta.to.shared.u64 t, %1; cvt.u32.u64 %0, t; }" : "=r"(a) : "l"(p));
    return a;
}
__device__ __forceinline__ void ldmx4(uint32_t* r, uint32_t addr) {
    asm volatile("ldmatrix.sync.aligned.m8n8.x4.shared.b16 {%0,%1,%2,%3}, [%4];"
                 : "=r"(r[0]), "=r"(r[1]), "=r"(r[2]), "=r"(r[3]) : "r"(addr));
}
__device__ __forceinline__ void ldmx2(uint32_t* r, uint32_t addr) {
    asm volatile("ldmatrix.sync.aligned.m8n8.x2.shared.b16 {%0,%1}, [%2];"
                 : "=r"(r[0]), "=r"(r[1]) : "r"(addr));
}
__device__ __forceinline__ void mma16816(float* c, const uint32_t* a, const uint32_t* b) {
    asm volatile(
        "mma.sync.aligned.m16n8k16.row.col.f32.bf16.bf16.f32 "
        "{%0,%1,%2,%3}, {%4,%5,%6,%7}, {%8,%9}, {%0,%1,%2,%3};"
        : "+f"(c[0]), "+f"(c[1]), "+f"(c[2]), "+f"(c[3])
        : "r"(a[0]), "r"(a[1]), "r"(a[2]), "r"(a[3]), "r"(b[0]), "r"(b[1]));
}
__device__ __forceinline__ uint32_t pack_bf16(float x, float y) {
    return (uint32_t)__bfloat16_as_ushort(__float2bfloat16_rn(x))
         | ((uint32_t)__bfloat16_as_ushort(__float2bfloat16_rn(y)) << 16);
}
__device__ __forceinline__ void cp_async16(uint32_t dst, const void* src) {
    asm volatile("cp.async.cg.shared.global [%0], [%1], 16;" :: "r"(dst), "l"(src) : "memory");
}
// exact bf16 -> fp32 (bit shift)
__device__ __forceinline__ float bflo(uint32_t w) { return __uint_as_float(w << 16); }
__device__ __forceinline__ float bfhi(uint32_t w) { return __uint_as_float(w & 0xFFFF0000u); }

#define PADB 80          // bytes per smem tile row (64B data + 16B pad)
// ---- logits (128q x 64k CTA) ----
#define LGS_B_OFF 10240                  // B rows start (A = 128 rows)
#define LGS_STAGE (10240 + 64 * PADB)    // 15360 B per stage
#define LG_SMEM   (3 * LGS_STAGE)        // 46080
#define EPI_STRIDE 144                   // staging row stride (bytes)
// ---- proj ----
#define PR_SMEM (2 * 128 * PADB)

// ===========================================================================
// projection: qk[B*S,512] = x @ W^T + bias, single bf16 HMMA.
// Head of kernel also zeros g_z / g_w / out (512 CTAs cover all; completes
// before logits/colw/out consume them in stream order).
// ===========================================================================
__global__ __launch_bounds__(256, 2) void proj_kernel(
    const float* __restrict__ x, const float* __restrict__ W,
    const float* __restrict__ bias, float* __restrict__ out, int n_out)
{
    __shared__ __align__(16) char tiles[PR_SMEM];

    const int tid = threadIdx.x;
    const int cta = blockIdx.y * gridDim.x + blockIdx.x;   // 0..511

    // ---- folded zeroing: 512 CTAs x 256 thr cover 131072 slots ----
    {
        int i = cta * 256 + tid;                 // 0..131071
        if (i < BB * SS) { g_z[i] = 0.0f; g_w[i] = 0.0f; }
        if (i < n_out)   out[i] = 0.0f;
    }

    const int lane = tid & 31, wid = tid >> 5;
    const int wm = wid >> 2, wn = wid & 3;

    const float* Ab = x + (size_t)blockIdx.y * 128 * DD;
    const float* Bb = W + (size_t)blockIdx.x * 128 * DD;
    const uint32_t sb = smem_u32(tiles);

    float acc[4][4][4];
#pragma unroll
    for (int m = 0; m < 4; m++)
#pragma unroll
        for (int n = 0; n < 4; n++)
#pragma unroll
            for (int u = 0; u < 4; u++) acc[m][n][u] = 0.0f;

    const uint32_t a_row = (uint32_t)(lane & 15);
    const uint32_t a_koff = (uint32_t)((lane >> 4) << 4);
    const uint32_t b_row = (uint32_t)(lane & 7);
    const uint32_t b_koff = (uint32_t)(((lane >> 3) & 1) << 4);

    for (int kt = 0; kt < 8; kt++) {
        __syncthreads();
#pragma unroll
        for (int i = 0; i < 8; i++) {
            int chunk = tid + i * 256;
            int arr = chunk >> 10;
            int c = chunk & 1023;
            int row = c >> 3, c4 = c & 7;
            const float* src = (arr ? Bb : Ab) + (size_t)row * DD + kt * 32 + c4 * 4;
            float4 v = *reinterpret_cast<const float4*>(src);
            uint2 p;
            p.x = pack_bf16(v.x, v.y);
            p.y = pack_bf16(v.z, v.w);
            *reinterpret_cast<uint2*>(tiles + arr * 10240 + row * PADB + c4 * 8) = p;
        }
        __syncthreads();

#pragma unroll
        for (int k16 = 0; k16 < 2; k16++) {
            const uint32_t kb = (uint32_t)(k16 * 32);
            uint32_t bh[4][2];
#pragma unroll
            for (int n = 0; n < 4; n++) {
                uint32_t boff = (uint32_t)(wn * 32 + n * 8 + b_row) * PADB + kb + b_koff;
                ldmx2(bh[n], sb + 10240 + boff);
            }
#pragma unroll
            for (int m = 0; m < 4; m++) {
                uint32_t aoff = (uint32_t)(wm * 64 + m * 16 + a_row) * PADB + kb + a_koff;
                uint32_t ah[4];
                ldmx4(ah, sb + aoff);
#pragma unroll
                for (int n = 0; n < 4; n++)
                    mma16816(acc[m][n], ah, bh[n]);
            }
        }
    }

    const int g = lane >> 2, t2 = (lane & 3) * 2;
#pragma unroll
    for (int m = 0; m < 4; m++) {
        const size_t grow = (size_t)blockIdx.y * 128 + wm * 64 + m * 16 + g;
#pragma unroll
        for (int n = 0; n < 4; n++) {
            const int col = blockIdx.x * 128 + wn * 32 + n * 8 + t2;
            const float b0 = bias[col], b1 = bias[col + 1];
            uint32_t p01 = pack_bf16(acc[m][n][0] + b0, acc[m][n][1] + b1);
            uint32_t p23 = pack_bf16(acc[m][n][2] + b0, acc[m][n][3] + b1);
            __nv_bfloat16* base = (col < DD) ? (g_q + col) : (g_k + (col - DD));
            *reinterpret_cast<uint32_t*>(base + grow * DD)       = p01;
            *reinterpret_cast<uint32_t*>(base + (grow + 8) * DD) = p23;
        }
    }
}

// ===========================================================================
// logits kernel (round-11 best config): CTA = 128(q) x 64(k), K=256,
// single bf16 HMMA. 8 warps 4m x 2n, warp tile 32x32, 4 CTAs/SM (64-reg).
// 3-stage cp.async, hoisted ldmatrix bases.
// STAGED epilogue: exp -> smem (stride 144) -> 16B-coalesced store; z sums.
// ===========================================================================
__global__ __launch_bounds__(256, 4) void logits_kernel() {
    extern __shared__ __align__(16) char tiles[];
    __shared__ float zrow[128];

    const int tid = threadIdx.x;
    const int lane = tid & 31, wid = tid >> 5;
    const int wm = wid & 3, wn = wid >> 2;      // 4 m-groups x 2 n-groups
    const int nt = blockIdx.x, qt = blockIdx.y, b = blockIdx.z;

    if (tid < 128) zrow[tid] = 0.0f;

    const uint32_t sb = smem_u32(tiles);
    const __nv_bfloat16* Qs = g_q + ((size_t)b * SS + (size_t)qt * 128) * DD;
    const __nv_bfloat16* Ks = g_k + ((size_t)b * SS + (size_t)nt * 64) * DD;

    float acc[2][4][4];
#pragma unroll
    for (int m = 0; m < 2; m++)
#pragma unroll
        for (int n = 0; n < 4; n++)
#pragma unroll
            for (int u = 0; u < 4; u++) acc[m][n][u] = 0.0f;

    // hoisted per-thread ldmatrix base addresses (smem absolute, stage 0)
    const uint32_t x4_row = (uint32_t)(lane & 15);
    const uint32_t x4_koff = (uint32_t)((lane >> 4) << 4);
    const uint32_t a_base0 = sb + (uint32_t)(wm * 32 + x4_row) * PADB + x4_koff;
    const uint32_t a_base1 = a_base0 + 16 * PADB;
    const uint32_t b_base0 = sb + LGS_B_OFF + (uint32_t)(wn * 32 + x4_row) * PADB + x4_koff;
    const uint32_t b_base1 = b_base0 + 16 * PADB;

    const int ch_isB[3]  = { tid >= 512 ? 1 : 0, (tid + 256) >= 512 ? 1 : 0, 1 };

#define LOAD_STAGE(kt, s)                                                        \
    do {                                                                         \
        _Pragma("unroll")                                                        \
        for (int i = 0; i < 3; i++) {                                            \
            int chunk = tid + i * 256;                                           \
            int isB = ch_isB[i];                                                 \
            int c = chunk - (isB ? 512 : 0);                                     \
            int row = c >> 2, c4 = c & 3;                                        \
            const __nv_bfloat16* src = (isB ? Ks : Qs) + (size_t)row * DD + (kt) * 32 + c4 * 8; \
            cp_async16(sb + (uint32_t)(s) * LGS_STAGE + (isB ? LGS_B_OFF : 0) + row * PADB + c4 * 16, src); \
        }                                                                        \
        asm volatile("cp.async.commit_group;" ::: "memory");                     \
    } while (0)

    LOAD_STAGE(0, 0);
    LOAD_STAGE(1, 1);

    int stage = 0;
    for (int kt = 0; kt < 8; kt++) {
        if (kt < 7) asm volatile("cp.async.wait_group 1;" ::: "memory");
        else        asm volatile("cp.async.wait_group 0;" ::: "memory");
        __syncthreads();
        if (kt + 2 < 8) {
            int ns = stage + 2; if (ns >= 3) ns -= 3;
            LOAD_STAGE(kt + 2, ns);
        }

        const uint32_t soff = (uint32_t)stage * LGS_STAGE;
#pragma unroll
        for (int k16 = 0; k16 < 2; k16++) {
            const uint32_t kb = soff + (uint32_t)(k16 * 32);
            uint32_t br[2][4];
            ldmx4(br[0], b_base0 + kb);
            ldmx4(br[1], b_base1 + kb);
            uint32_t ah[4];
            ldmx4(ah, a_base0 + kb);
#pragma unroll
            for (int nn = 0; nn < 2; nn++) {
                uint32_t b0[2] = { br[nn][0], br[nn][2] };
                uint32_t b1[2] = { br[nn][1], br[nn][3] };
                mma16816(acc[0][nn * 2 + 0], ah, b0);
                mma16816(acc[0][nn * 2 + 1], ah, b1);
            }
            ldmx4(ah, a_base1 + kb);
#pragma unroll
            for (int nn = 0; nn < 2; nn++) {
                uint32_t b0[2] = { br[nn][0], br[nn][2] };
                uint32_t b1[2] = { br[nn][1], br[nn][3] };
                mma16816(acc[1][nn * 2 + 0], ah, b0);
                mma16816(acc[1][nn * 2 + 1], ah, b1);
            }
        }
        if (++stage == 3) stage = 0;
    }
    __syncthreads();   // mainloop reads done; smem becomes P staging

    // ---- epilogue: exp, pack to smem (128 rows x 64 bf16, stride 144) ----
    const int g = lane >> 2, t2 = (lane & 3) * 2;
#pragma unroll
    for (int m = 0; m < 2; m++) {
        const int row_lo = wm * 32 + m * 16 + g;
        float zlo = 0.0f, zhi = 0.0f;
#pragma unroll
        for (int n = 0; n < 4; n++) {
            float e0 = __expf(acc[m][n][0] * 0.0625f);
            float e1 = __expf(acc[m][n][1] * 0.0625f);
            float e2 = __expf(acc[m][n][2] * 0.0625f);
            float e3 = __expf(acc[m][n][3] * 0.0625f);
            zlo += e0 + e1;
            zhi += e2 + e3;
            const int col = wn * 32 + n * 8 + t2;
            *reinterpret_cast<uint32_t*>(tiles + row_lo * EPI_STRIDE + col * 2)       = pack_bf16(e0, e1);
            *reinterpret_cast<uint32_t*>(tiles + (row_lo + 8) * EPI_STRIDE + col * 2) = pack_bf16(e2, e3);
        }
        atomicAdd(&zrow[row_lo], zlo);
        atomicAdd(&zrow[row_lo + 8], zhi);
    }
    __syncthreads();

    // ---- coalesced 16B stores: 128 rows x 128 B = 1024 chunks, 4/thread ----
    const size_t grow0 = (size_t)b * SS + (size_t)qt * 128;
#pragma unroll
    for (int i = 0; i < 4; i++) {
        int chunk = tid + i * 256;
        int row = chunk >> 3, c16 = chunk & 7;
        uint4 v = *reinterpret_cast<const uint4*>(tiles + row * EPI_STRIDE + c16 * 16);
        *reinterpret_cast<uint4*>(g_P + (grow0 + row) * SS + nt * 64 + c16 * 8) = v;
    }
    if (tid < 128)
        atomicAdd(&g_z[grow0 + tid], zrow[tid]);
}

// ===========================================================================
// column weights: w_k += sum_q P[q,k] / z_q.  Column-partitioned:
// block = (512 q-rows) x (128 cols); 1024 blocks. Coalesced 256B row reads,
// register accumulators, smem cross-stripe reduce, 128 atomics/block.
// ===========================================================================
__global__ __launch_bounds__(256) void col_weights_kernel() {
    __shared__ float izs[512];
    __shared__ float ws[16][128];

    const int tid = threadIdx.x;
    const int r0 = blockIdx.x * 512;
    const int c0 = blockIdx.y * 128;
    const int b  = blockIdx.z;

    for (int i = tid; i < 512; i += 256)
        izs[i] = 1.0f / g_z[(size_t)b * SS + r0 + i];
    __syncthreads();

    const int c8 = tid & 15;
    const int rstripe = tid >> 4;

    float acc[8];
#pragma unroll
    for (int j = 0; j < 8; j++) acc[j] = 0.0f;

    const __nv_bfloat16* Pb = g_P + ((size_t)b * SS + r0 + rstripe) * SS + c0 + c8 * 8;
#pragma unroll 4
    for (int i = 0; i < 32; i++) {
        const float iz = izs[rstripe + i * 16];
        uint4 v = *reinterpret_cast<const uint4*>(Pb + (size_t)i * 16 * SS);
        const uint32_t w[4] = {v.x, v.y, v.z, v.w};
#pragma unroll
        for (int h = 0; h < 4; h++) {
            acc[2 * h]     = fmaf(bflo(w[h]), iz, acc[2 * h]);
            acc[2 * h + 1] = fmaf(bfhi(w[h]), iz, acc[2 * h + 1]);
        }
    }

#pragma unroll
    for (int j = 0; j < 8; j++) ws[rstripe][c8 * 8 + j] = acc[j];
    __syncthreads();

    if (tid < 128) {
        float s = 0.0f;
#pragma unroll
        for (int j = 0; j < 16; j++) s += ws[j][tid];
        atomicAdd(&g_w[(size_t)b * SS + c0 + tid], s);
    }
}

// ===========================================================================
// weighted pool: out[b,d] = sum_k w[b,k] * x[b,k,d]
// ===========================================================================
__global__ void out_kernel(const float* __restrict__ x, float* __restrict__ out) {
    const int b = blockIdx.y;
    const int k0 = blockIdx.x * 64;
    const int d = threadIdx.x;

    const float* xp = x + ((size_t)b * SS + k0) * DD + d;
    const float* wp = g_w + (size_t)b * SS + k0;
    float acc = 0.0f;
#pragma unroll 8
    for (int kk = 0; kk < 64; kk++)
        acc = fmaf(wp[kk], xp[(size_t)kk * DD], acc);
    atomicAdd(&out[b * DD + d], acc);
}

// ===========================================================================
extern "C" void kernel_launch(void* const* d_in, const int* in_sizes, int n_in,
                              void* d_out, int out_size) {
    const float* x    = (const float*)d_in[0];
    const float* W    = (const float*)d_in[1];
    const float* bias = (const float*)d_in[2];
    float* out = (float*)d_out;

    cudaFuncSetAttribute(logits_kernel, cudaFuncAttributeMaxDynamicSharedMemorySize, LG_SMEM);

    // 1) projection + folded zeroing                         (launch #1)
    {
        dim3 grid(D2 / 128, (BB * SS) / 128);
        proj_kernel<<<grid, 256>>>(x, W, bias, out, out_size);
    }

    // 2) logits + exp + z  (round-11 best config)            (launch #2)
    {
        dim3 grid(SS / 64, SS / 128, BB);
        logits_kernel<<<grid, 256, LG_SMEM>>>();
    }

    // 3) column weights                                      (launch #3)
    {
        dim3 grid(SS / 512, SS / 128, BB);
        col_weights_kernel<<<grid, 256>>>();
    }

    // 4) weighted pool                                       (launch #4)
    out_kernel<<<dim3(64, BB), 256>>>(x, out);
}